// round 2
// baseline (speedup 1.0000x reference)
#include <cuda_runtime.h>
#include <math.h>

#define NN   96
#define LAT  256
#define INSZ (NN*NN)      // 9216
#define OUTD 4656         // 96*97/2
#define PAD  97
#define ITERS 50

// ---------------- scratch (device globals; no allocation allowed) ----------
__device__ float g_P1[2][36][LAT];
__device__ float g_P2[37][LAT];
__device__ float g_mu[LAT];
__device__ float g_ls[LAT];
__device__ float g_y[LAT];
__device__ float g_out[OUTD];
__device__ float g_rec[INSZ];

// ---------------- triangular index helpers --------------------------------
__device__ __forceinline__ int triu_base(int r) { return r*NN - (r*(r-1))/2; }
__device__ __forceinline__ int triu_row(int m) {
    int r = (int)((193.0 - sqrt(37249.0 - 8.0*(double)m)) * 0.5);
    if (r < 0) r = 0; if (r > NN-1) r = NN-1;
    while (r > 0 && triu_base(r) > m) r--;
    while (r < NN-1 && triu_base(r+1) <= m) r++;
    return r;
}

// ---------------- stage 1: mu / logstd GEMV partials -----------------------
__global__ void k_gemv1(const float* __restrict__ h,
                        const float* __restrict__ Wmu,
                        const float* __restrict__ Wls) {
    int bx = blockIdx.x, which = blockIdx.y, t = threadIdx.x;
    const float* W = which ? Wls : Wmu;
    __shared__ float sh[256];
    int i0 = bx * 256;
    sh[t] = h[i0 + t];
    __syncthreads();
    float acc = 0.f;
    const float* Wp = W + (size_t)i0 * LAT + t;
#pragma unroll 8
    for (int r = 0; r < 256; r++) acc += sh[r] * Wp[(size_t)r * LAT];
    g_P1[which][bx][t] = acc;
}

__global__ void k_red1(const float* __restrict__ bmu, const float* __restrict__ bls) {
    int w = blockIdx.x, t = threadIdx.x;
    float s = w ? bls[t] : bmu[t];
    for (int b = 0; b < 36; b++) s += g_P1[w][b][t];
    if (w) g_ls[t] = s; else g_mu[t] = s;
}

// ---------------- stage 2: y = relu([h, mu] @ W_d1 + b) --------------------
__global__ void k_gemv2(const float* __restrict__ h, const float* __restrict__ Wd1) {
    int bx = blockIdx.x, t = threadIdx.x;
    __shared__ float sh[256];
    int i0 = bx * 256;
    int i = i0 + t;
    sh[t] = (i < INSZ) ? h[i] : g_mu[i - INSZ];
    __syncthreads();
    float acc = 0.f;
    const float* Wp = Wd1 + (size_t)i0 * LAT + t;
#pragma unroll 8
    for (int r = 0; r < 256; r++) acc += sh[r] * Wp[(size_t)r * LAT];
    g_P2[bx][t] = acc;
}

__global__ void k_red2(const float* __restrict__ bd1) {
    int t = threadIdx.x;
    float s = bd1[t];
    for (int b = 0; b < 37; b++) s += g_P2[b][t];
    g_y[t] = fmaxf(s, 0.f);
}

// ---------------- stage 3: out = sigmoid(y @ W_d2 + b), build rec ----------
__global__ void k_out(const float* __restrict__ Wd2, const float* __restrict__ bd2) {
    __shared__ float sy[LAT];
    int t = threadIdx.x;
    sy[t] = g_y[t];
    __syncthreads();
    int m = blockIdx.x * 256 + t;
    if (m >= OUTD) return;
    float acc = bd2[m];
    const float* Wp = Wd2 + m;
#pragma unroll 8
    for (int k = 0; k < LAT; k++) acc += sy[k] * Wp[(size_t)k * OUTD];
    float o = 1.f / (1.f + expf(-acc));
    g_out[m] = o;
    int r = triu_row(m);
    int c = r + (m - triu_base(r));
    g_rec[r*NN + c] = o;
    g_rec[c*NN + r] = o;
}

// ---------------- mega kernel: prep + MPM + Hungarian + loss ---------------
struct SM {
    float B[NN*PAD];
    float D[NN*PAD];
    float X[NN*PAD];
    float M[NN*PAD];
    float aval[NN*NN];
    float d_[NN], dr_[NN], nf_[NN], nfr_[NN];
    float red[32];
    float hu[PAD], hv[PAD], hminv[PAD];
    int   hway[PAD], hp[PAD], husd[PAD];
    int   acnt[NN];
    int   colrow[NN], ind[NN];
    short aidx[NN*NN];
};

__device__ void hungarian_warp(SM* s, int lane) {
    const unsigned FULL = 0xffffffffu;
    for (int idx = lane; idx < PAD; idx += 32) { s->hu[idx]=0.f; s->hv[idx]=0.f; s->hp[idx]=0; }
    __syncwarp();
    for (int i = 1; i <= NN; i++) {
        for (int idx = lane; idx < PAD; idx += 32) { s->hminv[idx]=1e30f; s->husd[idx]=0; }
        if (lane == 0) s->hp[0] = i;
        __syncwarp();
        int j0 = 0;
        while (true) {
            if (lane == 0) s->husd[j0] = 1;
            __syncwarp();
            int   i0  = s->hp[j0];
            float ui0 = s->hu[i0];
            float bestv = 1e30f; int bestj = 0x7fffffff;
#pragma unroll
            for (int q = 0; q < 3; q++) {
                int j = 1 + lane + q*32;
                if (!s->husd[j]) {
                    float cur = -s->X[(i0-1)*PAD + (j-1)] - ui0 - s->hv[j];
                    if (cur < s->hminv[j]) { s->hminv[j] = cur; s->hway[j] = j0; }
                    float mv = s->hminv[j];
                    if (mv < bestv || (mv == bestv && j < bestj)) { bestv = mv; bestj = j; }
                }
            }
            for (int off = 16; off; off >>= 1) {
                float ov = __shfl_down_sync(FULL, bestv, off);
                int   oj = __shfl_down_sync(FULL, bestj, off);
                if (ov < bestv || (ov == bestv && oj < bestj)) { bestv = ov; bestj = oj; }
            }
            float delta = __shfl_sync(FULL, bestv, 0);
            int   j1    = __shfl_sync(FULL, bestj, 0);
            __syncwarp();
#pragma unroll
            for (int q = 0; q < 3; q++) {
                int j = 1 + lane + q*32;
                if (s->husd[j]) { s->hu[s->hp[j]] += delta; s->hv[j] -= delta; }
                else             s->hminv[j] -= delta;
            }
            if (lane == 0) { s->hu[s->hp[0]] += delta; s->hv[0] -= delta; }
            __syncwarp();
            j0 = j1;
            if (s->hp[j0] == 0) break;
        }
        if (lane == 0) {
            int jj = j0;
            while (jj) { int jn = s->hway[jj]; s->hp[jj] = s->hp[jn]; jj = jn; }
        }
        __syncwarp();
    }
#pragma unroll
    for (int q = 0; q < 3; q++) { int j = 1 + lane + q*32; s->colrow[s->hp[j]-1] = j-1; }
    __syncwarp();
#pragma unroll
    for (int q = 0; q < 3; q++) { int r = lane + q*32; s->ind[s->colrow[r]] = r; }
    __syncwarp();
}

__global__ void __launch_bounds__(1024, 1)
k_mega(const float* __restrict__ adj, float* __restrict__ outp) {
    extern __shared__ char raw[];
    SM* s = (SM*)raw;
    int tid = threadIdx.x;
    const unsigned FULL = 0xffffffffu;

    // ---- prep: load rec->M(temp), adj->X(temp) ----
    for (int o = tid; o < INSZ; o += 1024) {
        int r = o / NN, c = o % NN;
        s->M[r*PAD + c] = g_rec[o];
        s->X[r*PAD + c] = adj[o];
    }
    __syncthreads();
    if (tid < NN) {
        int a = tid; float sr = 0.f, sa = 0.f;
        for (int b = 0; b < NN; b++) { sr += s->M[a*PAD+b]; sa += s->X[a*PAD+b]; }
        s->nfr_[a] = sr; s->nf_[a] = sa;
        s->dr_[a] = s->M[a*PAD+a]; s->d_[a] = s->X[a*PAD+a];
    }
    __syncthreads();
    for (int o = tid; o < INSZ; o += 1024) {
        int i = o / NN, j = o % NN;
        float ney = (i == j) ? 0.f : 1.f;
        s->B[i*PAD + j] = s->M[i*PAD+j] * s->dr_[i] * s->dr_[j] * ney;
        s->D[i*PAD + j] = s->d_[i] * s->dr_[j] / (fabsf(s->nf_[i] - s->nfr_[j]) + 1.0f);
    }
    if (tid < NN) {
        int i = tid, cnt = 0;
        for (int j = 0; j < NN; j++) {
            float v = (i == j) ? 0.f : s->X[i*PAD+j] * s->d_[i] * s->d_[j];
            if (v != 0.f) { s->aidx[i*NN+cnt] = (short)j; s->aval[i*NN+cnt] = v; cnt++; }
        }
        s->acnt[i] = cnt;
    }
    __syncthreads();
    for (int o = tid; o < INSZ; o += 1024) {
        int i = o / NN, j = o % NN;
        s->X[i*PAD + j] = 1.0f / (float)NN;
    }
    __syncthreads();

    // ---- MPM: 50 iterations ----
    const int tj  = tid >> 5;          // 0..31 (row tile)
    const int ta  = tid & 31;          // 0..31 (col tile)
    const int jr0 = tj * 3, ac0 = ta * 3;

    for (int it = 0; it < ITERS; it++) {
        // M[j][a] = max_b X[j][b] * B[a][b] ; 3x3 register tile
        float m00=0,m01=0,m02=0,m10=0,m11=0,m12=0,m20=0,m21=0,m22=0;
        const float* X0 = s->X + (jr0+0)*PAD;
        const float* X1 = s->X + (jr0+1)*PAD;
        const float* X2 = s->X + (jr0+2)*PAD;
        const float* B0 = s->B + (ac0+0)*PAD;
        const float* B1 = s->B + (ac0+1)*PAD;
        const float* B2 = s->B + (ac0+2)*PAD;
#pragma unroll 4
        for (int b = 0; b < NN; b++) {
            float x0 = X0[b], x1 = X1[b], x2 = X2[b];
            float b0 = B0[b], b1 = B1[b], b2 = B2[b];
            m00 = fmaxf(m00, x0*b0); m01 = fmaxf(m01, x0*b1); m02 = fmaxf(m02, x0*b2);
            m10 = fmaxf(m10, x1*b0); m11 = fmaxf(m11, x1*b1); m12 = fmaxf(m12, x1*b2);
            m20 = fmaxf(m20, x2*b0); m21 = fmaxf(m21, x2*b1); m22 = fmaxf(m22, x2*b2);
        }
        s->M[(jr0+0)*PAD+ac0+0]=m00; s->M[(jr0+0)*PAD+ac0+1]=m01; s->M[(jr0+0)*PAD+ac0+2]=m02;
        s->M[(jr0+1)*PAD+ac0+0]=m10; s->M[(jr0+1)*PAD+ac0+1]=m11; s->M[(jr0+1)*PAD+ac0+2]=m12;
        s->M[(jr0+2)*PAD+ac0+0]=m20; s->M[(jr0+2)*PAD+ac0+1]=m21; s->M[(jr0+2)*PAD+ac0+2]=m22;
        __syncthreads();

        // xn = X*D + A_sparse @ M  (3 rows x 3 cols per thread)
        float xn[3][3]; float sq = 0.f;
#pragma unroll
        for (int ir = 0; ir < 3; ir++) {
            int i = jr0 + ir;
            float s0 = 0.f, s1 = 0.f, s2 = 0.f;
            int cnt = s->acnt[i];
            const short* idx = s->aidx + i*NN;
            const float* val = s->aval + i*NN;
            for (int k = 0; k < cnt; k++) {
                int j = idx[k]; float v = val[k];
                const float* Mr = s->M + j*PAD + ac0;
                s0 += v * Mr[0]; s1 += v * Mr[1]; s2 += v * Mr[2];
            }
            const float* Xp = s->X + i*PAD + ac0;
            const float* Dp = s->D + i*PAD + ac0;
            xn[ir][0] = Xp[0]*Dp[0] + s0;
            xn[ir][1] = Xp[1]*Dp[1] + s1;
            xn[ir][2] = Xp[2]*Dp[2] + s2;
            sq += xn[ir][0]*xn[ir][0] + xn[ir][1]*xn[ir][1] + xn[ir][2]*xn[ir][2];
        }
        // Frobenius norm (deterministic two-level reduction)
        for (int off = 16; off; off >>= 1) sq += __shfl_down_sync(FULL, sq, off);
        if ((tid & 31) == 0) s->red[tid >> 5] = sq;
        __syncthreads();
        if (tid < 32) {
            float v = s->red[tid];
            for (int off = 16; off; off >>= 1) v += __shfl_down_sync(FULL, v, off);
            if (tid == 0) s->red[0] = 1.0f / sqrtf(v);
        }
        __syncthreads();
        float scale = s->red[0];
#pragma unroll
        for (int ir = 0; ir < 3; ir++) {
            s->X[(jr0+ir)*PAD+ac0+0] = xn[ir][0]*scale;
            s->X[(jr0+ir)*PAD+ac0+1] = xn[ir][1]*scale;
            s->X[(jr0+ir)*PAD+ac0+2] = xn[ir][2]*scale;
        }
        __syncthreads();
    }

    // ---- Hungarian on cost = -X (warp 0) ----
    if (tid < 32) hungarian_warp(s, tid);
    __syncthreads();

    // ---- bce + kl ----
    float acc = 0.f;
    for (int m = tid; m < OUTD; m += 1024) {
        int r = triu_row(m);
        int c = r + (m - triu_base(r));
        float av = adj[s->ind[r]*NN + s->ind[c]];
        float t  = g_out[m];
        acc += fmaxf(av, 0.f) - av*t + log1pf(expf(-fabsf(av)));
    }
    acc *= (1.0f / (float)OUTD);
    if (tid < LAT) {
        float lsv = g_ls[tid], muv = g_mu[tid];
        acc += (-0.5f / (float)INSZ) * (1.0f + lsv - muv*muv - expf(lsv));
    }
    for (int off = 16; off; off >>= 1) acc += __shfl_down_sync(FULL, acc, off);
    if ((tid & 31) == 0) s->red[tid >> 5] = acc;
    __syncthreads();
    if (tid < 32) {
        float v = s->red[tid];
        for (int off = 16; off; off >>= 1) v += __shfl_down_sync(FULL, v, off);
        if (tid == 0) outp[0] = v;
    }
}

// ---------------- launcher -------------------------------------------------
extern "C" void kernel_launch(void* const* d_in, const int* in_sizes, int n_in,
                              void* d_out, int out_size) {
    const float* h    = (const float*)d_in[0];
    const float* adjp = (const float*)d_in[1];
    const float* Wmu  = (const float*)d_in[2];
    const float* bmu  = (const float*)d_in[3];
    const float* Wls  = (const float*)d_in[4];
    const float* bls  = (const float*)d_in[5];
    const float* Wd1  = (const float*)d_in[6];
    const float* bd1  = (const float*)d_in[7];
    const float* Wd2  = (const float*)d_in[8];
    const float* bd2  = (const float*)d_in[9];

    cudaFuncSetAttribute(k_mega, cudaFuncAttributeMaxDynamicSharedMemorySize,
                         (int)sizeof(SM));

    k_gemv1<<<dim3(36, 2), 256>>>(h, Wmu, Wls);
    k_red1 <<<2, 256>>>(bmu, bls);
    k_gemv2<<<37, 256>>>(h, Wd1);
    k_red2 <<<1, 256>>>(bd1);
    k_out  <<<(OUTD + 255) / 256, 256>>>(Wd2, bd2);
    k_mega <<<1, 1024, sizeof(SM)>>>(adjp, (float*)d_out);
}

// round 3
// speedup vs baseline: 2.0481x; 2.0481x over previous
#include <cuda_runtime.h>
#include <math.h>

#define NN   96
#define LAT  256
#define INSZ (NN*NN)      // 9216
#define OUTD 4656         // 96*97/2
#define PAD  97
#define ITERS 50

// ---------------- scratch (device globals; no allocation allowed) ----------
__device__ float g_P1[2][36][LAT];
__device__ float g_P2[37][LAT];
__device__ float g_mu[LAT];
__device__ float g_ls[LAT];
__device__ float g_y[LAT];
__device__ float g_out[OUTD];
__device__ float g_rec[INSZ];

// ---------------- triangular index helpers --------------------------------
__device__ __forceinline__ int triu_base(int r) { return r*NN - (r*(r-1))/2; }
__device__ __forceinline__ int triu_row(int m) {
    int r = (int)((193.0 - sqrt(37249.0 - 8.0*(double)m)) * 0.5);
    if (r < 0) r = 0; if (r > NN-1) r = NN-1;
    while (r > 0 && triu_base(r) > m) r--;
    while (r < NN-1 && triu_base(r+1) <= m) r++;
    return r;
}

// ---------------- stage 1: mu / logstd GEMV partials -----------------------
__global__ void k_gemv1(const float* __restrict__ h,
                        const float* __restrict__ Wmu,
                        const float* __restrict__ Wls) {
    int bx = blockIdx.x, which = blockIdx.y, t = threadIdx.x;
    const float* W = which ? Wls : Wmu;
    __shared__ float sh[256];
    int i0 = bx * 256;
    sh[t] = h[i0 + t];
    __syncthreads();
    float acc = 0.f;
    const float* Wp = W + (size_t)i0 * LAT + t;
#pragma unroll 8
    for (int r = 0; r < 256; r++) acc += sh[r] * Wp[(size_t)r * LAT];
    g_P1[which][bx][t] = acc;
}

__global__ void k_red1(const float* __restrict__ bmu, const float* __restrict__ bls) {
    int w = blockIdx.x, t = threadIdx.x;
    float s = w ? bls[t] : bmu[t];
    for (int b = 0; b < 36; b++) s += g_P1[w][b][t];
    if (w) g_ls[t] = s; else g_mu[t] = s;
}

// ---------------- stage 2: y = relu([h, mu] @ W_d1 + b) --------------------
__global__ void k_gemv2(const float* __restrict__ h, const float* __restrict__ Wd1) {
    int bx = blockIdx.x, t = threadIdx.x;
    __shared__ float sh[256];
    int i0 = bx * 256;
    int i = i0 + t;
    sh[t] = (i < INSZ) ? h[i] : g_mu[i - INSZ];
    __syncthreads();
    float acc = 0.f;
    const float* Wp = Wd1 + (size_t)i0 * LAT + t;
#pragma unroll 8
    for (int r = 0; r < 256; r++) acc += sh[r] * Wp[(size_t)r * LAT];
    g_P2[bx][t] = acc;
}

__global__ void k_red2(const float* __restrict__ bd1) {
    int t = threadIdx.x;
    float s = bd1[t];
    for (int b = 0; b < 37; b++) s += g_P2[b][t];
    g_y[t] = fmaxf(s, 0.f);
}

// ---------------- stage 3: out = sigmoid(y @ W_d2 + b), build rec ----------
__global__ void k_out(const float* __restrict__ Wd2, const float* __restrict__ bd2) {
    __shared__ float sy[LAT];
    int t = threadIdx.x;
    sy[t] = g_y[t];
    __syncthreads();
    int m = blockIdx.x * 256 + t;
    if (m >= OUTD) return;
    float acc = bd2[m];
    const float* Wp = Wd2 + m;
#pragma unroll 8
    for (int k = 0; k < LAT; k++) acc += sy[k] * Wp[(size_t)k * OUTD];
    float o = 1.f / (1.f + expf(-acc));
    g_out[m] = o;
    int r = triu_row(m);
    int c = r + (m - triu_base(r));
    g_rec[r*NN + c] = o;
    g_rec[c*NN + r] = o;
}

// ---------------- mega kernel: prep + MPM + Hungarian + loss ---------------
struct SM {
    float B[NN*PAD];
    float D[NN*PAD];
    float X[NN*PAD];
    float M[NN*PAD];
    float aval[NN*NN];
    float d_[NN], dr_[NN], nf_[NN], nfr_[NN];
    float red[32];
    float u_s[PAD];
    int   way[PAD], p[PAD];
    int   acnt[NN];
    int   colrow[NN], ind[NN];
    short aidx[NN*NN];
};

// order-preserving float<->uint transforms (for unsigned min reduction)
__device__ __forceinline__ unsigned f2ord(float f) {
    unsigned b = __float_as_uint(f);
    return b ^ ((unsigned)((int)b >> 31) | 0x80000000u);
}
__device__ __forceinline__ float ord2f(unsigned u) {
    unsigned b = (u & 0x80000000u) ? (u ^ 0x80000000u) : ~u;
    return __uint_as_float(b);
}

// Warp-parallel Hungarian with O(1)-per-step deferred dual updates.
// cost[i][j] = -X[i][j]. Matches the reference's decisions exactly
// (strict-< key updates; lowest-index argmin tie-break).
__device__ void hungarian_warp(SM* s, int lane) {
    const unsigned FULL = 0xffffffffu;
    for (int idx = lane; idx < PAD; idx += 32) { s->u_s[idx] = 0.f; s->p[idx] = 0; }
    float vq[3] = {0.f, 0.f, 0.f};   // v[j] for cols j = lane+1, lane+33, lane+65
    __syncwarp();

    for (int i = 1; i <= NN; i++) {
        unsigned key[3] = {0xFFFFFFFFu, 0xFFFFFFFFu, 0xFFFFFFFFu};
        float du[3] = {0.f, 0.f, 0.f};
        int usedmask = 0;
        if (lane == 0) s->p[0] = i;
        __syncwarp();
        float Dlt = 0.f;          // running offset: Delta = sum of deltas so far
        int j0 = 0, i0 = i;

        for (;;) {
            // mark j0 as used (owner lane records Delta at marking time)
            if (j0 > 0) {
                int c0 = j0 - 1;
                if (lane == (c0 & 31)) {
                    int oq = c0 >> 5;
                    usedmask |= 1 << oq;
                    du[oq] = Dlt;
                }
            }
            float ui0 = s->u_s[i0];
            const float* Xr = s->X + (i0 - 1) * PAD;
            unsigned best = 0xFFFFFFFFu;
            unsigned bj = 0xFFFFFFFFu;
#pragma unroll
            for (int q = 0; q < 3; q++) {
                if (!((usedmask >> q) & 1)) {
                    int c = lane + q * 32;
                    // effective cur + Delta  (key-offset form)
                    float f = Dlt - Xr[c] - ui0 - vq[q];
                    unsigned kb = f2ord(f);
                    if (kb < key[q]) { key[q] = kb; s->way[c + 1] = j0; }
                    if (key[q] < best) { best = key[q]; bj = (unsigned)(c + 1); }
                }
            }
            unsigned gmin = __reduce_min_sync(FULL, best);
            unsigned cj   = (best == gmin) ? bj : 0xFFFFFFFFu;
            unsigned jmin = __reduce_min_sync(FULL, cj);
            Dlt = ord2f(gmin);            // Delta_new = keymin exactly
            j0 = (int)jmin;
            i0 = s->p[j0];
            if (i0 == 0) break;
        }

        // settle deferred dual updates (uses pre-augmentation p)
#pragma unroll
        for (int q = 0; q < 3; q++) {
            if ((usedmask >> q) & 1) {
                float amt = Dlt - du[q];
                vq[q] -= amt;
                int r = s->p[lane + q * 32 + 1];
                s->u_s[r] += amt;          // distinct rows -> no race
            }
        }
        if (lane == 0) s->u_s[i] += Dlt;   // p[0] = i, used since Delta=0
        __syncwarp();
        // augmenting path flip
        if (lane == 0) {
            int jj = j0;
            while (jj) { int j1 = s->way[jj]; s->p[jj] = s->p[j1]; jj = j1; }
        }
        __syncwarp();
    }
#pragma unroll
    for (int q = 0; q < 3; q++) { int c = lane + q*32; s->colrow[s->p[c+1] - 1] = c; }
    __syncwarp();
#pragma unroll
    for (int q = 0; q < 3; q++) { int r = lane + q*32; s->ind[s->colrow[r]] = r; }
    __syncwarp();
}

__global__ void __launch_bounds__(1024, 1)
k_mega(const float* __restrict__ adj, float* __restrict__ outp) {
    extern __shared__ char raw[];
    SM* s = (SM*)raw;
    int tid = threadIdx.x;
    const unsigned FULL = 0xffffffffu;

    // ---- prep: load rec->M(temp), adj->X(temp) ----
    for (int o = tid; o < INSZ; o += 1024) {
        int r = o / NN, c = o % NN;
        s->M[r*PAD + c] = g_rec[o];
        s->X[r*PAD + c] = adj[o];
    }
    __syncthreads();
    if (tid < NN) {
        int a = tid; float sr = 0.f, sa = 0.f;
        for (int b = 0; b < NN; b++) { sr += s->M[a*PAD+b]; sa += s->X[a*PAD+b]; }
        s->nfr_[a] = sr; s->nf_[a] = sa;
        s->dr_[a] = s->M[a*PAD+a]; s->d_[a] = s->X[a*PAD+a];
    }
    __syncthreads();
    for (int o = tid; o < INSZ; o += 1024) {
        int i = o / NN, j = o % NN;
        float ney = (i == j) ? 0.f : 1.f;
        s->B[i*PAD + j] = s->M[i*PAD+j] * s->dr_[i] * s->dr_[j] * ney;
        s->D[i*PAD + j] = s->d_[i] * s->dr_[j] / (fabsf(s->nf_[i] - s->nfr_[j]) + 1.0f);
    }
    if (tid < NN) {
        int i = tid, cnt = 0;
        for (int j = 0; j < NN; j++) {
            float v = (i == j) ? 0.f : s->X[i*PAD+j] * s->d_[i] * s->d_[j];
            if (v != 0.f) { s->aidx[i*NN+cnt] = (short)j; s->aval[i*NN+cnt] = v; cnt++; }
        }
        s->acnt[i] = cnt;
    }
    __syncthreads();
    for (int o = tid; o < INSZ; o += 1024) {
        int i = o / NN, j = o % NN;
        s->X[i*PAD + j] = 1.0f / (float)NN;
    }
    __syncthreads();

    // ---- MPM: 50 iterations ----
    const int tj  = tid >> 5;          // 0..31 (row tile)
    const int ta  = tid & 31;          // 0..31 (col tile)
    const int jr0 = tj * 3, ac0 = ta * 3;

    for (int it = 0; it < ITERS; it++) {
        // M[j][a] = max_b X[j][b] * B[a][b] ; 3x3 register tile
        float m00=0,m01=0,m02=0,m10=0,m11=0,m12=0,m20=0,m21=0,m22=0;
        const float* X0 = s->X + (jr0+0)*PAD;
        const float* X1 = s->X + (jr0+1)*PAD;
        const float* X2 = s->X + (jr0+2)*PAD;
        const float* B0 = s->B + (ac0+0)*PAD;
        const float* B1 = s->B + (ac0+1)*PAD;
        const float* B2 = s->B + (ac0+2)*PAD;
#pragma unroll 4
        for (int b = 0; b < NN; b++) {
            float x0 = X0[b], x1 = X1[b], x2 = X2[b];
            float b0 = B0[b], b1 = B1[b], b2 = B2[b];
            m00 = fmaxf(m00, x0*b0); m01 = fmaxf(m01, x0*b1); m02 = fmaxf(m02, x0*b2);
            m10 = fmaxf(m10, x1*b0); m11 = fmaxf(m11, x1*b1); m12 = fmaxf(m12, x1*b2);
            m20 = fmaxf(m20, x2*b0); m21 = fmaxf(m21, x2*b1); m22 = fmaxf(m22, x2*b2);
        }
        s->M[(jr0+0)*PAD+ac0+0]=m00; s->M[(jr0+0)*PAD+ac0+1]=m01; s->M[(jr0+0)*PAD+ac0+2]=m02;
        s->M[(jr0+1)*PAD+ac0+0]=m10; s->M[(jr0+1)*PAD+ac0+1]=m11; s->M[(jr0+1)*PAD+ac0+2]=m12;
        s->M[(jr0+2)*PAD+ac0+0]=m20; s->M[(jr0+2)*PAD+ac0+1]=m21; s->M[(jr0+2)*PAD+ac0+2]=m22;
        __syncthreads();

        // xn = X*D + A_sparse @ M  (3 rows x 3 cols per thread)
        float xn[3][3]; float sq = 0.f;
#pragma unroll
        for (int ir = 0; ir < 3; ir++) {
            int i = jr0 + ir;
            float s0 = 0.f, s1 = 0.f, s2 = 0.f;
            int cnt = s->acnt[i];
            const short* idx = s->aidx + i*NN;
            const float* val = s->aval + i*NN;
            for (int k = 0; k < cnt; k++) {
                int j = idx[k]; float v = val[k];
                const float* Mr = s->M + j*PAD + ac0;
                s0 += v * Mr[0]; s1 += v * Mr[1]; s2 += v * Mr[2];
            }
            const float* Xp = s->X + i*PAD + ac0;
            const float* Dp = s->D + i*PAD + ac0;
            xn[ir][0] = Xp[0]*Dp[0] + s0;
            xn[ir][1] = Xp[1]*Dp[1] + s1;
            xn[ir][2] = Xp[2]*Dp[2] + s2;
            sq += xn[ir][0]*xn[ir][0] + xn[ir][1]*xn[ir][1] + xn[ir][2]*xn[ir][2];
        }
        // Frobenius norm (deterministic two-level reduction)
        for (int off = 16; off; off >>= 1) sq += __shfl_down_sync(FULL, sq, off);
        if ((tid & 31) == 0) s->red[tid >> 5] = sq;
        __syncthreads();
        if (tid < 32) {
            float v = s->red[tid];
            for (int off = 16; off; off >>= 1) v += __shfl_down_sync(FULL, v, off);
            if (tid == 0) s->red[0] = 1.0f / sqrtf(v);
        }
        __syncthreads();
        float scale = s->red[0];
#pragma unroll
        for (int ir = 0; ir < 3; ir++) {
            s->X[(jr0+ir)*PAD+ac0+0] = xn[ir][0]*scale;
            s->X[(jr0+ir)*PAD+ac0+1] = xn[ir][1]*scale;
            s->X[(jr0+ir)*PAD+ac0+2] = xn[ir][2]*scale;
        }
        __syncthreads();
    }

    // ---- Hungarian on cost = -X (warp 0) ----
    if (tid < 32) hungarian_warp(s, tid);
    __syncthreads();

    // ---- bce + kl ----
    float acc = 0.f;
    for (int m = tid; m < OUTD; m += 1024) {
        int r = triu_row(m);
        int c = r + (m - triu_base(r));
        float av = adj[s->ind[r]*NN + s->ind[c]];
        float t  = g_out[m];
        acc += fmaxf(av, 0.f) - av*t + log1pf(expf(-fabsf(av)));
    }
    acc *= (1.0f / (float)OUTD);
    if (tid < LAT) {
        float lsv = g_ls[tid], muv = g_mu[tid];
        acc += (-0.5f / (float)INSZ) * (1.0f + lsv - muv*muv - expf(lsv));
    }
    for (int off = 16; off; off >>= 1) acc += __shfl_down_sync(FULL, acc, off);
    if ((tid & 31) == 0) s->red[tid >> 5] = acc;
    __syncthreads();
    if (tid < 32) {
        float v = s->red[tid];
        for (int off = 16; off; off >>= 1) v += __shfl_down_sync(FULL, v, off);
        if (tid == 0) outp[0] = v;
    }
}

// ---------------- launcher -------------------------------------------------
extern "C" void kernel_launch(void* const* d_in, const int* in_sizes, int n_in,
                              void* d_out, int out_size) {
    const float* h    = (const float*)d_in[0];
    const float* adjp = (const float*)d_in[1];
    const float* Wmu  = (const float*)d_in[2];
    const float* bmu  = (const float*)d_in[3];
    const float* Wls  = (const float*)d_in[4];
    const float* bls  = (const float*)d_in[5];
    const float* Wd1  = (const float*)d_in[6];
    const float* bd1  = (const float*)d_in[7];
    const float* Wd2  = (const float*)d_in[8];
    const float* bd2  = (const float*)d_in[9];

    cudaFuncSetAttribute(k_mega, cudaFuncAttributeMaxDynamicSharedMemorySize,
                         (int)sizeof(SM));

    k_gemv1<<<dim3(36, 2), 256>>>(h, Wmu, Wls);
    k_red1 <<<2, 256>>>(bmu, bls);
    k_gemv2<<<37, 256>>>(h, Wd1);
    k_red2 <<<1, 256>>>(bd1);
    k_out  <<<(OUTD + 255) / 256, 256>>>(Wd2, bd2);
    k_mega <<<1, 1024, sizeof(SM)>>>(adjp, (float*)d_out);
}

// round 4
// speedup vs baseline: 2.5171x; 1.2290x over previous
#include <cuda_runtime.h>
#include <math.h>
#include <stddef.h>

#define NN   96
#define LAT  256
#define INSZ (NN*NN)      // 9216
#define OUTD 4656         // 96*97/2
#define PAD  97
#define ITERS 50
#define CSZ  4            // cluster size
#define ROWS_PER_CTA (NN/CSZ)   // 24

// ---------------- scratch (device globals; no allocation allowed) ----------
__device__ float g_P1[2][36][LAT];
__device__ float g_P2[37][LAT];
__device__ float g_mu[LAT];
__device__ float g_ls[LAT];
__device__ float g_y[LAT];
__device__ float g_out[OUTD];
__device__ float g_rec[INSZ];

// ---------------- cluster PTX helpers --------------------------------------
__device__ __forceinline__ unsigned ctarank() {
    unsigned r; asm("mov.u32 %0, %%cluster_ctarank;" : "=r"(r)); return r;
}
__device__ __forceinline__ unsigned smem_u32(const void* p) {
    unsigned a;
    asm("{ .reg .u64 t; cvta.to.shared.u64 t, %1; cvt.u32.u64 %0, t; }"
        : "=r"(a) : "l"(p));
    return a;
}
__device__ __forceinline__ unsigned mapa_rank(unsigned saddr, unsigned rank) {
    unsigned r;
    asm("mapa.shared::cluster.u32 %0, %1, %2;" : "=r"(r) : "r"(saddr), "r"(rank));
    return r;
}
__device__ __forceinline__ void stc(unsigned addr, float v) {
    asm volatile("st.shared::cluster.b32 [%0], %1;"
                 :: "r"(addr), "r"(__float_as_uint(v)) : "memory");
}
#define CLUSTER_SYNC() do { \
    asm volatile("barrier.cluster.arrive.aligned;" ::: "memory"); \
    asm volatile("barrier.cluster.wait.aligned;"   ::: "memory"); } while (0)

// ---------------- triangular index helpers --------------------------------
__device__ __forceinline__ int triu_base(int r) { return r*NN - (r*(r-1))/2; }
__device__ __forceinline__ int triu_row(int m) {
    int r = (int)((193.0 - sqrt(37249.0 - 8.0*(double)m)) * 0.5);
    if (r < 0) r = 0; if (r > NN-1) r = NN-1;
    while (r > 0 && triu_base(r) > m) r--;
    while (r < NN-1 && triu_base(r+1) <= m) r++;
    return r;
}

// ---------------- stage 1: mu / logstd GEMV partials -----------------------
__global__ void k_gemv1(const float* __restrict__ h,
                        const float* __restrict__ Wmu,
                        const float* __restrict__ Wls) {
    int bx = blockIdx.x, which = blockIdx.y, t = threadIdx.x;
    const float* W = which ? Wls : Wmu;
    __shared__ float sh[256];
    int i0 = bx * 256;
    sh[t] = h[i0 + t];
    __syncthreads();
    float acc = 0.f;
    const float* Wp = W + (size_t)i0 * LAT + t;
#pragma unroll 8
    for (int r = 0; r < 256; r++) acc += sh[r] * Wp[(size_t)r * LAT];
    g_P1[which][bx][t] = acc;
}

__global__ void k_red1(const float* __restrict__ bmu, const float* __restrict__ bls) {
    int w = blockIdx.x, t = threadIdx.x;
    float s = w ? bls[t] : bmu[t];
    for (int b = 0; b < 36; b++) s += g_P1[w][b][t];
    if (w) g_ls[t] = s; else g_mu[t] = s;
}

// ---------------- stage 2: y = relu([h, mu] @ W_d1 + b) --------------------
__global__ void k_gemv2(const float* __restrict__ h, const float* __restrict__ Wd1) {
    int bx = blockIdx.x, t = threadIdx.x;
    __shared__ float sh[256];
    int i0 = bx * 256;
    int i = i0 + t;
    sh[t] = (i < INSZ) ? h[i] : g_mu[i - INSZ];
    __syncthreads();
    float acc = 0.f;
    const float* Wp = Wd1 + (size_t)i0 * LAT + t;
#pragma unroll 8
    for (int r = 0; r < 256; r++) acc += sh[r] * Wp[(size_t)r * LAT];
    g_P2[bx][t] = acc;
}

__global__ void k_red2(const float* __restrict__ bd1) {
    int t = threadIdx.x;
    float s = bd1[t];
    for (int b = 0; b < 37; b++) s += g_P2[b][t];
    g_y[t] = fmaxf(s, 0.f);
}

// ---------------- stage 3: out = sigmoid(y @ W_d2 + b), build rec ----------
__global__ void k_out(const float* __restrict__ Wd2, const float* __restrict__ bd2) {
    __shared__ float sy[LAT];
    int t = threadIdx.x;
    sy[t] = g_y[t];
    __syncthreads();
    int m = blockIdx.x * 256 + t;
    if (m >= OUTD) return;
    float acc = bd2[m];
    const float* Wp = Wd2 + m;
#pragma unroll 8
    for (int k = 0; k < LAT; k++) acc += sy[k] * Wp[(size_t)k * OUTD];
    float o = 1.f / (1.f + expf(-acc));
    g_out[m] = o;
    int r = triu_row(m);
    int c = r + (m - triu_base(r));
    g_rec[r*NN + c] = o;
    g_rec[c*NN + r] = o;
}

// ---------------- mega kernel: prep + MPM + Hungarian + loss ---------------
struct SM {
    float B[NN*PAD];
    float D[NN*PAD];
    float X[NN*PAD];
    float M[NN*PAD];
    float aval[NN*NN];
    float d_[NN], dr_[NN], nf_[NN], nfr_[NN];
    float red[32];
    float npart[32];
    float u_s[PAD];
    int2  pu[PAD];
    int   way[PAD], p[PAD];
    int   acnt[NN];
    int   colrow[NN], ind[NN];
    short aidx[NN*NN];
};
#define SOFF(f) ((unsigned)offsetof(SM, f))

// order-preserving float<->uint transforms (for unsigned min reduction)
__device__ __forceinline__ unsigned f2ord(float f) {
    unsigned b = __float_as_uint(f);
    return b ^ ((unsigned)((int)b >> 31) | 0x80000000u);
}
__device__ __forceinline__ float ord2f(unsigned u) {
    unsigned b = (u & 0x80000000u) ? (u ^ 0x80000000u) : ~u;
    return __uint_as_float(b);
}

// Warp-parallel Hungarian, O(1) per step, packed (p,u) lookups,
// single REDUX + ballots for argmin-j (numpy-compatible tie-break).
__device__ void hungarian_warp(SM* s, int lane) {
    const unsigned FULL = 0xffffffffu;
    const unsigned MAXU = 0xffffffffu;
    for (int j = lane; j < PAD; j += 32) { s->u_s[j] = 0.f; s->p[j] = 0; }
    float vq0 = 0.f, vq1 = 0.f, vq2 = 0.f;
    __syncwarp();

    for (int i = 1; i <= NN; i++) {
        if (lane == 0) s->p[0] = i;
        __syncwarp();
        // rebuild packed pu[j] = { u[p[j]], p[j] }
        for (int j = lane; j < PAD; j += 32) {
            int pj = s->p[j];
            int2 e; e.x = __float_as_int(s->u_s[pj]); e.y = pj;
            s->pu[j] = e;
        }
        __syncwarp();

        unsigned key0 = MAXU, key1 = MAXU, key2 = MAXU;
        float du0 = 0.f, du1 = 0.f, du2 = 0.f;
        int usedmask = 0;
        float Dlt = 0.f;
        float ui0 = s->u_s[i];
        int j0 = 0, i0 = i;

        for (;;) {
            // mark previous j0 as used (owner lane)
            if (j0 > 0) {
                int c0 = j0 - 1;
                if (lane == (c0 & 31)) {
                    int oq = c0 >> 5;
                    usedmask |= 1 << oq;
                    if      (oq == 0) { du0 = Dlt; key0 = MAXU; }
                    else if (oq == 1) { du1 = Dlt; key1 = MAXU; }
                    else              { du2 = Dlt; key2 = MAXU; }
                }
            }
            const float* Xr = s->X + (i0 - 1) * PAD;
            float t0 = Dlt - ui0;
            {
                float f = t0 - Xr[lane] - vq0;
                unsigned kb = f2ord(f);
                if (kb < key0 && !(usedmask & 1)) { key0 = kb; s->way[lane + 1] = j0; }
            }
            {
                float f = t0 - Xr[lane + 32] - vq1;
                unsigned kb = f2ord(f);
                if (kb < key1 && !(usedmask & 2)) { key1 = kb; s->way[lane + 33] = j0; }
            }
            {
                float f = t0 - Xr[lane + 64] - vq2;
                unsigned kb = f2ord(f);
                if (kb < key2 && !(usedmask & 4)) { key2 = kb; s->way[lane + 65] = j0; }
            }
            unsigned best = min(key0, min(key1, key2));
            unsigned gmin = __reduce_min_sync(FULL, best);
            unsigned b0 = __ballot_sync(FULL, key0 == gmin);
            unsigned b1 = __ballot_sync(FULL, key1 == gmin);
            unsigned b2 = __ballot_sync(FULL, key2 == gmin);
            Dlt = ord2f(gmin);
            j0 = b0 ? __ffs(b0) : (b1 ? 32 + __ffs(b1) : 64 + __ffs(b2));
            int2 e = s->pu[j0];
            i0 = e.y;
            if (i0 == 0) break;
            ui0 = __int_as_float(e.x);
        }

        // settle deferred dual updates (pre-augmentation p)
        if (usedmask & 1) { float amt = Dlt - du0; vq0 -= amt; s->u_s[s->p[lane +  1]] += amt; }
        if (usedmask & 2) { float amt = Dlt - du1; vq1 -= amt; s->u_s[s->p[lane + 33]] += amt; }
        if (usedmask & 4) { float amt = Dlt - du2; vq2 -= amt; s->u_s[s->p[lane + 65]] += amt; }
        if (lane == 0) s->u_s[i] += Dlt;
        __syncwarp();
        if (lane == 0) {
            int jj = j0;
            while (jj) { int j1 = s->way[jj]; s->p[jj] = s->p[j1]; jj = j1; }
        }
        __syncwarp();
    }
#pragma unroll
    for (int q = 0; q < 3; q++) { int c = lane + q*32; s->colrow[s->p[c+1] - 1] = c; }
    __syncwarp();
#pragma unroll
    for (int q = 0; q < 3; q++) { int r = lane + q*32; s->ind[s->colrow[r]] = r; }
    __syncwarp();
}

__global__ void __launch_bounds__(1024, 1)
k_mega(const float* __restrict__ adj, float* __restrict__ outp) {
    extern __shared__ char raw[];
    SM* s = (SM*)raw;
    int tid  = threadIdx.x;
    int warp = tid >> 5, lane = tid & 31;
    const unsigned FULL = 0xffffffffu;

    unsigned rk    = ctarank();
    unsigned sbase = smem_u32(raw);
    unsigned rb[CSZ];
#pragma unroll
    for (int r = 0; r < CSZ; r++) rb[r] = mapa_rank(sbase, (unsigned)r);

    // ---- prep (full, replicated per CTA): rec->M(temp), adj->X(temp) ----
    for (int o = tid; o < INSZ; o += 1024) {
        int r = o / NN, c = o % NN;
        s->M[r*PAD + c] = g_rec[o];
        s->X[r*PAD + c] = adj[o];
    }
    __syncthreads();
    if (tid < NN) {
        int a = tid; float sr = 0.f, sa = 0.f;
        for (int b = 0; b < NN; b++) { sr += s->M[a*PAD+b]; sa += s->X[a*PAD+b]; }
        s->nfr_[a] = sr; s->nf_[a] = sa;
        s->dr_[a] = s->M[a*PAD+a]; s->d_[a] = s->X[a*PAD+a];
    }
    __syncthreads();
    for (int o = tid; o < INSZ; o += 1024) {
        int i = o / NN, j = o % NN;
        float ney = (i == j) ? 0.f : 1.f;
        s->B[i*PAD + j] = s->M[i*PAD+j] * s->dr_[i] * s->dr_[j] * ney;
        s->D[i*PAD + j] = s->d_[i] * s->dr_[j] / (fabsf(s->nf_[i] - s->nfr_[j]) + 1.0f);
    }
    if (tid < NN) {
        int i = tid, cnt = 0;
        for (int j = 0; j < NN; j++) {
            float v = (i == j) ? 0.f : s->X[i*PAD+j] * s->d_[i] * s->d_[j];
            if (v != 0.f) { s->aidx[i*NN+cnt] = (short)j; s->aval[i*NN+cnt] = v; cnt++; }
        }
        s->acnt[i] = cnt;
    }
    __syncthreads();
    for (int o = tid; o < INSZ; o += 1024) {
        int i = o / NN, j = o % NN;
        s->X[i*PAD + j] = 1.0f / (float)NN;
    }
    CLUSTER_SYNC();   // prep done everywhere before any peer M writes arrive

    // ---- MPM: 50 iterations, rows split across 4 CTAs ----
    const int base0 = (int)rk * ROWS_PER_CTA;
    const int jr0 = base0 + warp * 3;     // valid for warp < 8
    const int ac0 = lane * 3;

    for (int it = 0; it < ITERS; it++) {
        if (warp < 8) {
            // M[j][a] = max_b X[j][b] * B[a][b] ; 3x3 register tile
            float m[3][3];
#pragma unroll
            for (int a = 0; a < 3; a++)
#pragma unroll
                for (int b = 0; b < 3; b++) m[a][b] = 0.f;
            const float* X0 = s->X + (jr0+0)*PAD;
            const float* X1 = s->X + (jr0+1)*PAD;
            const float* X2 = s->X + (jr0+2)*PAD;
            const float* B0 = s->B + (ac0+0)*PAD;
            const float* B1 = s->B + (ac0+1)*PAD;
            const float* B2 = s->B + (ac0+2)*PAD;
#pragma unroll 4
            for (int b = 0; b < NN; b++) {
                float x0 = X0[b], x1 = X1[b], x2 = X2[b];
                float c0 = B0[b], c1 = B1[b], c2 = B2[b];
                m[0][0] = fmaxf(m[0][0], x0*c0); m[0][1] = fmaxf(m[0][1], x0*c1); m[0][2] = fmaxf(m[0][2], x0*c2);
                m[1][0] = fmaxf(m[1][0], x1*c0); m[1][1] = fmaxf(m[1][1], x1*c1); m[1][2] = fmaxf(m[1][2], x1*c2);
                m[2][0] = fmaxf(m[2][0], x2*c0); m[2][1] = fmaxf(m[2][1], x2*c1); m[2][2] = fmaxf(m[2][2], x2*c2);
            }
            // broadcast tile into every CTA's M
#pragma unroll
            for (int ir = 0; ir < 3; ir++)
#pragma unroll
                for (int c = 0; c < 3; c++) {
                    unsigned off = SOFF(M) + (unsigned)((jr0+ir)*PAD + ac0 + c) * 4u;
                    float v = m[ir][c];
                    stc(rb[0] + off, v); stc(rb[1] + off, v);
                    stc(rb[2] + off, v); stc(rb[3] + off, v);
                }
        }
        CLUSTER_SYNC();   // full M visible everywhere

        float xn[3][3];
        if (warp < 8) {
            // xn = X*D + A_sparse @ M  (own 3 rows x 3 cols per thread)
            float sq = 0.f;
#pragma unroll
            for (int ir = 0; ir < 3; ir++) {
                int i = jr0 + ir;
                float s0 = 0.f, s1 = 0.f, s2 = 0.f;
                int cnt = s->acnt[i];
                const short* idx = s->aidx + i*NN;
                const float* val = s->aval + i*NN;
                for (int k = 0; k < cnt; k++) {
                    int j = idx[k]; float v = val[k];
                    const float* Mr = s->M + j*PAD + ac0;
                    s0 += v * Mr[0]; s1 += v * Mr[1]; s2 += v * Mr[2];
                }
                const float* Xp = s->X + i*PAD + ac0;
                const float* Dp = s->D + i*PAD + ac0;
                xn[ir][0] = Xp[0]*Dp[0] + s0;
                xn[ir][1] = Xp[1]*Dp[1] + s1;
                xn[ir][2] = Xp[2]*Dp[2] + s2;
                sq += xn[ir][0]*xn[ir][0] + xn[ir][1]*xn[ir][1] + xn[ir][2]*xn[ir][2];
            }
            for (int off = 16; off; off >>= 1) sq += __shfl_down_sync(FULL, sq, off);
            if (lane == 0) {
                unsigned off = SOFF(npart) + (unsigned)(8*(int)rk + warp) * 4u;
                stc(rb[0] + off, sq); stc(rb[1] + off, sq);
                stc(rb[2] + off, sq); stc(rb[3] + off, sq);
            }
        }
        CLUSTER_SYNC();   // all 32 partials visible everywhere

        if (warp == 0) {   // identical reduction order to single-CTA version
            float v = s->npart[lane];
            for (int off = 16; off; off >>= 1) v += __shfl_down_sync(FULL, v, off);
            if (lane == 0) s->red[0] = 1.0f / sqrtf(v);
        }
        __syncthreads();
        if (warp < 8) {
            float scale = s->red[0];
#pragma unroll
            for (int ir = 0; ir < 3; ir++) {
                s->X[(jr0+ir)*PAD+ac0+0] = xn[ir][0]*scale;
                s->X[(jr0+ir)*PAD+ac0+1] = xn[ir][1]*scale;
                s->X[(jr0+ir)*PAD+ac0+2] = xn[ir][2]*scale;
            }
            __syncwarp();
        }
    }

    // ---- gather all X rows into CTA 0 for the Hungarian phase ----
    if (warp < 8) {
#pragma unroll
        for (int ir = 0; ir < 3; ir++)
#pragma unroll
            for (int c = 0; c < 3; c++) {
                int row = jr0 + ir, col = ac0 + c;
                unsigned off = SOFF(X) + (unsigned)(row*PAD + col) * 4u;
                stc(rb[0] + off, s->X[row*PAD + col]);
            }
    }
    CLUSTER_SYNC();
    if (rk != 0) return;

    // ---- Hungarian on cost = -X (CTA 0, warp 0) ----
    if (tid < 32) hungarian_warp(s, tid);
    __syncthreads();

    // ---- bce + kl ----
    float acc = 0.f;
    for (int m = tid; m < OUTD; m += 1024) {
        int r = triu_row(m);
        int c = r + (m - triu_base(r));
        float av = adj[s->ind[r]*NN + s->ind[c]];
        float t  = g_out[m];
        acc += fmaxf(av, 0.f) - av*t + log1pf(expf(-fabsf(av)));
    }
    acc *= (1.0f / (float)OUTD);
    if (tid < LAT) {
        float lsv = g_ls[tid], muv = g_mu[tid];
        acc += (-0.5f / (float)INSZ) * (1.0f + lsv - muv*muv - expf(lsv));
    }
    for (int off = 16; off; off >>= 1) acc += __shfl_down_sync(FULL, acc, off);
    if (lane == 0) s->red[warp] = acc;
    __syncthreads();
    if (tid < 32) {
        float v = s->red[tid];
        for (int off = 16; off; off >>= 1) v += __shfl_down_sync(FULL, v, off);
        if (tid == 0) outp[0] = v;
    }
}

// ---------------- launcher -------------------------------------------------
extern "C" void kernel_launch(void* const* d_in, const int* in_sizes, int n_in,
                              void* d_out, int out_size) {
    const float* h    = (const float*)d_in[0];
    const float* adjp = (const float*)d_in[1];
    const float* Wmu  = (const float*)d_in[2];
    const float* bmu  = (const float*)d_in[3];
    const float* Wls  = (const float*)d_in[4];
    const float* bls  = (const float*)d_in[5];
    const float* Wd1  = (const float*)d_in[6];
    const float* bd1  = (const float*)d_in[7];
    const float* Wd2  = (const float*)d_in[8];
    const float* bd2  = (const float*)d_in[9];

    cudaFuncSetAttribute(k_mega, cudaFuncAttributeMaxDynamicSharedMemorySize,
                         (int)sizeof(SM));

    k_gemv1<<<dim3(36, 2), 256>>>(h, Wmu, Wls);
    k_red1 <<<2, 256>>>(bmu, bls);
    k_gemv2<<<37, 256>>>(h, Wd1);
    k_red2 <<<1, 256>>>(bd1);
    k_out  <<<(OUTD + 255) / 256, 256>>>(Wd2, bd2);

    cudaLaunchConfig_t cfg = {};
    cfg.gridDim  = dim3(CSZ, 1, 1);
    cfg.blockDim = dim3(1024, 1, 1);
    cfg.dynamicSmemBytes = sizeof(SM);
    cfg.stream = 0;
    cudaLaunchAttribute at[1];
    at[0].id = cudaLaunchAttributeClusterDimension;
    at[0].val.clusterDim.x = CSZ;
    at[0].val.clusterDim.y = 1;
    at[0].val.clusterDim.z = 1;
    cfg.attrs = at;
    cfg.numAttrs = 1;
    cudaLaunchKernelEx(&cfg, k_mega, adjp, (float*)d_out);
}